// round 15
// baseline (speedup 1.0000x reference)
#include <cuda_runtime.h>
#include <cstdint>

// ---------------------------------------------------------------------------
// Problem constants
// ---------------------------------------------------------------------------
#define TT   2048      // B*S total rows
#define DIM  7168
#define NH   64        // heads
#define HD   128       // head dim
#define RD   64        // rope dims
#define QL   1536
#define HHD  8192      // NH*HD
#define SQ   1024      // sequence (per batch)
#define EPSV 1e-6f
#define SCALEV 0.08838834764831845f   // 128^-0.5
#define KSPL 8         // split-K factor for the kw GEMM

// pair permutation within 8-element k-groups: fragments (qd, qd+4) -> adjacent
#define KPERM(k) (((k) & ~7) | (((k) & 3) << 1) | (((k) >> 2) & 1))

// merged-prep grid partition
#define PREP_QR  (TT * QL / 4 / 256)            // 3072 blocks
#define PREP_X   (TT * DIM / 4 / 256)           // 14336 blocks
#define PREP_TR  ((HHD / 32) * (QL / 32))       // 12288 blocks
#define PREP_PK  (8 * (DIM / 32))               // 1792 blocks
#define PREP_TOTAL (PREP_QR + PREP_X + PREP_TR + PREP_PK)

// ---------------------------------------------------------------------------
// Scratch (device globals: allocation-free, graph-capture safe)
// ---------------------------------------------------------------------------
__device__ unsigned g_q[TT * HHD];          // 64 MB : q tf32 bits, k-permuted
__device__ unsigned g_qrt[TT * QL];         // 12.6MB: qr tf32 bits, k-permuted
__device__ unsigned g_xt[TT * DIM];         // 58 MB : x  tf32 bits, k-permuted
__device__ unsigned g_wqt[HHD * QL];        // 50 MB : Wq^T tf32 bits, k-permuted
__device__ unsigned g_bkw[256 * DIM];       // 7.3MB : (Wk||Wproj||0)^T tf32, permuted
__device__ float    g_kwp[KSPL * TT * 256]; // 16 MB : split-K partials
__device__ float    g_w[TT * NH];           // per-head weights
__device__ unsigned g_ktf[TT * HD];         // final k, tf32 bits, k-permuted

// ---------------------------------------------------------------------------
// helpers
// ---------------------------------------------------------------------------
__device__ __forceinline__ unsigned f2tf(float f) {
    unsigned u;
    asm("cvt.rna.tf32.f32 %0, %1;" : "=r"(u) : "f"(f));
    return u;
}

__device__ __forceinline__ uint32_t smem_u32(const void* p) {
    uint32_t a;
    asm("{ .reg .u64 t; cvta.to.shared.u64 t, %1; cvt.u32.u64 %0, t; }"
        : "=r"(a) : "l"(p));
    return a;
}

#define CP_ASYNC16(dst, src) \
    asm volatile("cp.async.cg.shared.global [%0], [%1], 16;" \
                 :: "r"(dst), "l"(src) : "memory")
#define CP_COMMIT() asm volatile("cp.async.commit_group;" ::: "memory")
#define CP_WAIT(n)  asm volatile("cp.async.wait_group %0;" :: "n"(n) : "memory")

__device__ __forceinline__ void mma_tf32(float c[4], const unsigned a[4],
                                         const unsigned b[2]) {
    asm volatile(
        "mma.sync.aligned.m16n8k8.row.col.f32.tf32.tf32.f32 "
        "{%0,%1,%2,%3}, {%4,%5,%6,%7}, {%8,%9}, {%0,%1,%2,%3};"
        : "+f"(c[0]), "+f"(c[1]), "+f"(c[2]), "+f"(c[3])
        : "r"(a[0]), "r"(a[1]), "r"(a[2]), "r"(a[3]), "r"(b[0]), "r"(b[1]));
}

// smem tile row stride: 32 k + 8 pad u32 = 160 B (conflict-free LDS.64 pattern)
#define RST 40
#define TS_B_OFF 20480                     // 128 * 160
#define STAGE_BYTES 40960                  // A + B tiles per stage
#define SMEM_PIPE (2 * STAGE_BYTES)        // 81920  (2 CTAs/SM -> 160KB, safe)

// ---------------------------------------------------------------------------
// MERGED operand prep: one grid, four independent jobs (tf32 + KPERM).
// ---------------------------------------------------------------------------
__global__ __launch_bounds__(256) void prep_all(const float* __restrict__ qr,
                                                const float* __restrict__ x,
                                                const float* __restrict__ wqb,
                                                const float* __restrict__ wk,
                                                const float* __restrict__ wpr,
                                                unsigned* __restrict__ qrt,
                                                unsigned* __restrict__ xt,
                                                unsigned* __restrict__ wqt,
                                                unsigned* __restrict__ bkw) {
    const int tid = threadIdx.x;
    int b = blockIdx.x;

    if (b < PREP_QR) {
        const size_t i0 = ((size_t)b * 256 + tid) * 4;
        float4 v = *(const float4*)(qr + i0);
        qrt[KPERM(i0 + 0)] = f2tf(v.x);
        qrt[KPERM(i0 + 1)] = f2tf(v.y);
        qrt[KPERM(i0 + 2)] = f2tf(v.z);
        qrt[KPERM(i0 + 3)] = f2tf(v.w);
        return;
    }
    b -= PREP_QR;
    if (b < PREP_X) {
        const size_t i0 = ((size_t)b * 256 + tid) * 4;
        float4 v = *(const float4*)(x + i0);
        xt[KPERM(i0 + 0)] = f2tf(v.x);
        xt[KPERM(i0 + 1)] = f2tf(v.y);
        xt[KPERM(i0 + 2)] = f2tf(v.z);
        xt[KPERM(i0 + 3)] = f2tf(v.w);
        return;
    }
    b -= PREP_X;

    __shared__ float tile[32][33];
    const int tx = tid & 31, ty = tid >> 5;

    if (b < PREP_TR) {
        const int n0 = (b % (HHD / 32)) * 32;
        const int k0 = (b / (HHD / 32)) * 32;
#pragma unroll
        for (int j = 0; j < 32; j += 8)
            tile[ty + j][tx] = wqb[(size_t)(k0 + ty + j) * HHD + n0 + tx];
        __syncthreads();
#pragma unroll
        for (int j = 0; j < 32; j += 8)
            wqt[(size_t)(n0 + ty + j) * QL + KPERM(k0 + tx)] = f2tf(tile[tx][ty + j]);
        return;
    }
    b -= PREP_TR;
    {
        const int n0 = (b % 8) * 32;
        const int k0 = (b / 8) * 32;
#pragma unroll
        for (int j = 0; j < 32; j += 8) {
            int k = k0 + ty + j, n = n0 + tx;
            float v = (n < HD) ? wk[(size_t)k * HD + n]
                               : ((n < HD + NH) ? wpr[(size_t)k * NH + (n - HD)] : 0.f);
            tile[ty + j][tx] = v;
        }
        __syncthreads();
#pragma unroll
        for (int j = 0; j < 32; j += 8)
            bkw[(size_t)(n0 + ty + j) * DIM + KPERM(k0 + tx)] = f2tf(tile[tx][ty + j]);
    }
}

// ---------------------------------------------------------------------------
// MERGED double-buffered mma.sync tf32 GEMM; single-sync pipeline:
//   wait(load i) -> sync -> issue load(i+1) -> MMA(i)      (R12 best loop)
// Per-thread fragment offsets hoisted out of the chunk loop.
// ---------------------------------------------------------------------------
__global__ __launch_bounds__(256, 2) void mega_gemm(const unsigned* __restrict__ qrt,
                                                    const unsigned* __restrict__ wqt,
                                                    unsigned* __restrict__ qout,
                                                    const unsigned* __restrict__ xt,
                                                    const unsigned* __restrict__ bkw,
                                                    float* __restrict__ kwp,
                                                    const float* __restrict__ cosv,
                                                    const float* __restrict__ sinv) {
    extern __shared__ char smem[];
    const uint32_t sb = smem_u32(smem);
    const int tid = threadIdx.x;
    const int lane = tid & 31, wid = tid >> 5;
    const int warp_m = wid >> 2, warp_n = wid & 3;
    const int g = lane >> 2, qd = lane & 3;

    // hoisted per-thread fragment offsets (u32 units, loop-invariant)
    int aoff[4], boff[4];
#pragma unroll
    for (int mt = 0; mt < 4; mt++) aoff[mt] = (warp_m * 64 + mt * 16 + g) * RST + qd * 2;
#pragma unroll
    for (int nt = 0; nt < 4; nt++) boff[nt] = (warp_n * 32 + nt * 8 + g) * RST + qd * 2;

    const int bid = blockIdx.x;
    const bool is_q = (bid < 1024);

    const unsigned *A, *B;
    int m0, n0, Ktot, nchunks, c0, N;
    float* Cf;
    if (is_q) {
        m0 = (bid >> 6) * 128;
        n0 = (bid & 63) * 128;
        Ktot = QL; nchunks = QL / 32; c0 = 0; N = HHD;
        A = qrt; B = wqt; Cf = nullptr;
    } else {
        int b2 = bid - 1024;
        int z  = b2 >> 5;
        int r  = b2 & 31;
        m0 = (r >> 1) * 128;
        n0 = (r & 1) * 128;
        Ktot = DIM; nchunks = DIM / 32 / KSPL; c0 = z * nchunks; N = 256;
        A = xt; B = bkw; Cf = kwp + (size_t)z * TT * 256;
    }

    auto load_stage = [&](int c, int s) {
        const int kt = c * 32;
        const uint32_t base = sb + s * STAGE_BYTES;
#pragma unroll
        for (int r = 0; r < 4; r++) {
            int lin = r * 256 + tid;
            int row = lin >> 3, c4 = lin & 7;
            CP_ASYNC16(base + row * 160 + c4 * 16,
                       A + (size_t)(m0 + row) * Ktot + kt + c4 * 4);
        }
#pragma unroll
        for (int r = 0; r < 4; r++) {
            int lin = r * 256 + tid;
            int row = lin >> 3, c4 = lin & 7;
            CP_ASYNC16(base + TS_B_OFF + row * 160 + c4 * 16,
                       B + (size_t)(n0 + row) * Ktot + kt + c4 * 4);
        }
        CP_COMMIT();
    };

    float acc[4][4][4];
#pragma unroll
    for (int i = 0; i < 4; i++)
#pragma unroll
        for (int j = 0; j < 4; j++)
#pragma unroll
            for (int r = 0; r < 4; r++) acc[i][j][r] = 0.f;

    load_stage(c0, 0);

    for (int i = 0; i < nchunks; i++) {
        const int s = i & 1;
        CP_WAIT(0);
        __syncthreads();
        if (i + 1 < nchunks) load_stage(c0 + i + 1, s ^ 1);

        const unsigned* As = (const unsigned*)(smem + s * STAGE_BYTES);
        const unsigned* Bs = (const unsigned*)(smem + s * STAGE_BYTES + TS_B_OFF);
#pragma unroll
        for (int k8 = 0; k8 < 4; k8++) {
            const int ko = k8 * 8;
            unsigned a[4][4], b[4][2];
#pragma unroll
            for (int mt = 0; mt < 4; mt++) {
                uint2 lo = *(const uint2*)&As[aoff[mt] + ko];
                uint2 hi = *(const uint2*)&As[aoff[mt] + 8 * RST + ko];
                a[mt][0] = lo.x; a[mt][1] = hi.x; a[mt][2] = lo.y; a[mt][3] = hi.y;
            }
#pragma unroll
            for (int nt = 0; nt < 4; nt++) {
                uint2 bv = *(const uint2*)&Bs[boff[nt] + ko];
                b[nt][0] = bv.x; b[nt][1] = bv.y;
            }
#pragma unroll
            for (int mt = 0; mt < 4; mt++)
#pragma unroll
                for (int nt = 0; nt < 4; nt++) mma_tf32(acc[mt][nt], a[mt], b[nt]);
        }
    }

#pragma unroll
    for (int mt = 0; mt < 4; mt++) {
        int r0 = m0 + warp_m * 64 + mt * 16 + g;
#pragma unroll
        for (int nt = 0; nt < 4; nt++) {
            int cc = n0 + warp_n * 32 + nt * 8 + qd * 2;
            float v00 = acc[mt][nt][0], v01 = acc[mt][nt][1];
            float v10 = acc[mt][nt][2], v11 = acc[mt][nt][3];
            if (is_q) {
                int d = cc & (HD - 1);
                if (d < RD) {
                    float c0r = cosv[(size_t)r0 * RD + d];
                    float s0r = sinv[(size_t)r0 * RD + d];
                    float c1r = cosv[(size_t)(r0 + 8) * RD + d];
                    float s1r = sinv[(size_t)(r0 + 8) * RD + d];
                    float o00 = v00 * c0r - v01 * s0r;
                    float o01 = v01 * c0r + v00 * s0r;
                    float o10 = v10 * c1r - v11 * s1r;
                    float o11 = v11 * c1r + v10 * s1r;
                    v00 = o00; v01 = o01; v10 = o10; v11 = o11;
                }
                int p0 = KPERM(cc), p1 = KPERM(cc + 1);
                qout[(size_t)r0 * N + p0]       = f2tf(v00);
                qout[(size_t)r0 * N + p1]       = f2tf(v01);
                qout[(size_t)(r0 + 8) * N + p0] = f2tf(v10);
                qout[(size_t)(r0 + 8) * N + p1] = f2tf(v11);
            } else {
                *(float2*)(Cf + (size_t)r0 * N + cc)       = make_float2(v00, v01);
                *(float2*)(Cf + (size_t)(r0 + 8) * N + cc) = make_float2(v10, v11);
            }
        }
    }
}

// ---------------------------------------------------------------------------
// Fused: reduce split-K partials + LayerNorm + RoPE (threads 0-127 -> g_ktf)
//        + per-head weights (threads 128-191 -> g_w).
// ---------------------------------------------------------------------------
__global__ __launch_bounds__(192) void ln_rope_w(const float* __restrict__ kwp,
                                                 const float* __restrict__ cosv,
                                                 const float* __restrict__ sinv,
                                                 const float* __restrict__ gamma,
                                                 const float* __restrict__ beta,
                                                 unsigned* __restrict__ kout,
                                                 float* __restrict__ wout) {
    const int t = blockIdx.x;
    const int d = threadIdx.x;

    float v = 0.f;
#pragma unroll
    for (int z = 0; z < KSPL; z++)
        v += kwp[(size_t)z * TT * 256 + (size_t)t * 256 + d];

    __shared__ float r1[4], r2[4];
    __shared__ float ks[HD];

    if (d < HD) {
        float s1 = v, s2 = v * v;
#pragma unroll
        for (int off = 16; off; off >>= 1) {
            s1 += __shfl_xor_sync(0xffffffffu, s1, off);
            s2 += __shfl_xor_sync(0xffffffffu, s2, off);
        }
        if ((d & 31) == 0) { r1[d >> 5] = s1; r2[d >> 5] = s2; }
    }
    __syncthreads();

    if (d < HD) {
        float sum = r1[0] + r1[1] + r1[2] + r1[3];
        float sq  = r2[0] + r2[1] + r2[2] + r2[3];
        float mu  = sum * (1.f / HD);
        float var = sq * (1.f / HD) - mu * mu;
        float kn  = (v - mu) * rsqrtf(var + EPSV) * gamma[d] + beta[d];
        ks[d] = kn;
    }
    __syncthreads();

    if (d < HD) {
        float kn = ks[d];
        float out = kn;
        if (d < RD) {
            float c = cosv[t * RD + (d & ~1)];
            float s = sinv[t * RD + (d & ~1)];
            float partner = ks[d ^ 1];
            out = ((d & 1) == 0) ? (kn * c - partner * s)
                                 : (kn * c + partner * s);
        }
        kout[(size_t)t * HD + KPERM(d)] = f2tf(out);
    } else {
        wout[(size_t)t * NH + (d - HD)] = v;
    }
}

// ---------------------------------------------------------------------------
// scores: block = 2 queries (128 rows) x 128 keys, 256 threads, 2 CTAs/SM.
// Single-sync pipeline, LDS.64 fragments (R12 best loop), hoisted offsets.
// ---------------------------------------------------------------------------
__global__ __launch_bounds__(256, 2) void scores_tc(const unsigned* __restrict__ q,
                                                    const unsigned* __restrict__ ktf,
                                                    const float* __restrict__ w,
                                                    float* __restrict__ out) {
    extern __shared__ char smem[];
    const uint32_t sb = smem_u32(smem);
    const int tid = threadIdx.x;
    const int lane = tid & 31, wid = tid >> 5;
    const int warp_m = wid >> 2, warp_n = wid & 3;
    const int g = lane >> 2, qd = lane & 3;

    int aoff[4], boff[4];
#pragma unroll
    for (int mt = 0; mt < 4; mt++) aoff[mt] = (warp_m * 64 + mt * 16 + g) * RST + qd * 2;
#pragma unroll
    for (int nt = 0; nt < 4; nt++) boff[nt] = (warp_n * 32 + nt * 8 + g) * RST + qd * 2;

    const int t0 = blockIdx.y * 2;
    const int b  = t0 >> 10;
    const int k0 = blockIdx.x * 128;

    const float* wrow = w + (size_t)(t0 + warp_m) * NH;
    float w0[4], w1[4];
#pragma unroll
    for (int mt = 0; mt < 4; mt++) {
        w0[mt] = wrow[mt * 16 + g] * SCALEV;
        w1[mt] = wrow[mt * 16 + g + 8] * SCALEV;
    }

    const unsigned* qbase = q + (size_t)t0 * HHD;
    const unsigned* kbase = ktf + (size_t)(b * SQ + k0) * HD;

    auto load_stage = [&](int c, int s) {
        const int d0 = c * 32;
        const uint32_t base = sb + s * STAGE_BYTES;
#pragma unroll
        for (int r = 0; r < 4; r++) {
            int lin = r * 256 + tid;
            int row = lin >> 3, c4 = lin & 7;
            CP_ASYNC16(base + row * 160 + c4 * 16,
                       qbase + (size_t)(row >> 6) * HHD + (row & 63) * HD + d0 + c4 * 4);
        }
#pragma unroll
        for (int r = 0; r < 4; r++) {
            int lin = r * 256 + tid;
            int row = lin >> 3, c4 = lin & 7;
            CP_ASYNC16(base + TS_B_OFF + row * 160 + c4 * 16,
                       kbase + (size_t)row * HD + d0 + c4 * 4);
        }
        CP_COMMIT();
    };

    float acc[4][4][4];
#pragma unroll
    for (int i = 0; i < 4; i++)
#pragma unroll
        for (int j2 = 0; j2 < 4; j2++)
#pragma unroll
            for (int r = 0; r < 4; r++) acc[i][j2][r] = 0.f;

    load_stage(0, 0);

#pragma unroll
    for (int i = 0; i < 4; i++) {
        const int s = i & 1;
        CP_WAIT(0);
        __syncthreads();
        if (i + 1 < 4) load_stage(i + 1, s ^ 1);

        const unsigned* Qs = (const unsigned*)(smem + s * STAGE_BYTES);
        const unsigned* Ks = (const unsigned*)(smem + s * STAGE_BYTES + TS_B_OFF);
#pragma unroll
        for (int k8 = 0; k8 < 4; k8++) {
            const int ko = k8 * 8;
            unsigned a[4][4], bfr[4][2];
#pragma unroll
            for (int mt = 0; mt < 4; mt++) {
                uint2 lo = *(const uint2*)&Qs[aoff[mt] + ko];
                uint2 hi = *(const uint2*)&Qs[aoff[mt] + 8 * RST + ko];
                a[mt][0] = lo.x; a[mt][1] = hi.x; a[mt][2] = lo.y; a[mt][3] = hi.y;
            }
#pragma unroll
            for (int nt = 0; nt < 4; nt++) {
                uint2 bv = *(const uint2*)&Ks[boff[nt] + ko];
                bfr[nt][0] = bv.x; bfr[nt][1] = bv.y;
            }
#pragma unroll
            for (int mt = 0; mt < 4; mt++)
#pragma unroll
                for (int nt = 0; nt < 4; nt++) mma_tf32(acc[mt][nt], a[mt], bfr[nt]);
        }
    }

    // weighted relu + head reduction (intra-warp shfl)
    float p[4][2];
#pragma unroll
    for (int nt = 0; nt < 4; nt++) { p[nt][0] = 0.f; p[nt][1] = 0.f; }
#pragma unroll
    for (int mt = 0; mt < 4; mt++) {
#pragma unroll
        for (int nt = 0; nt < 4; nt++) {
            p[nt][0] += w0[mt] * fmaxf(acc[mt][nt][0], 0.f)
                      + w1[mt] * fmaxf(acc[mt][nt][2], 0.f);
            p[nt][1] += w0[mt] * fmaxf(acc[mt][nt][1], 0.f)
                      + w1[mt] * fmaxf(acc[mt][nt][3], 0.f);
        }
    }
#pragma unroll
    for (int nt = 0; nt < 4; nt++) {
#pragma unroll
        for (int off = 4; off <= 16; off <<= 1) {
            p[nt][0] += __shfl_xor_sync(0xffffffffu, p[nt][0], off);
            p[nt][1] += __shfl_xor_sync(0xffffffffu, p[nt][1], off);
        }
    }

    if (lane < 4) {
        float* o = out + (size_t)(t0 + warp_m) * SQ + k0 + warp_n * 32;
#pragma unroll
        for (int nt = 0; nt < 4; nt++)
            *(float2*)(o + nt * 8 + lane * 2) = make_float2(p[nt][0], p[nt][1]);
    }
}

// ---------------------------------------------------------------------------
// launch
// ---------------------------------------------------------------------------
extern "C" void kernel_launch(void* const* d_in, const int* in_sizes, int n_in,
                              void* d_out, int out_size) {
    const float* x    = (const float*)d_in[0];   // [2048, 7168]
    const float* qr   = (const float*)d_in[1];   // [2048, 1536]
    const float* cosv = (const float*)d_in[2];   // [2048, 64]
    const float* sinv = (const float*)d_in[3];   // [2048, 64]
    const float* wqb  = (const float*)d_in[4];   // [1536, 8192]
    const float* wk   = (const float*)d_in[5];   // [7168, 128]
    const float* wpr  = (const float*)d_in[6];   // [7168, 64]
    const float* gam  = (const float*)d_in[7];   // [128]
    const float* bet  = (const float*)d_in[8];   // [128]
    float* out = (float*)d_out;

    float *kwp, *wv;
    unsigned *q, *qrt, *xt, *wqt, *bkw, *ktf;
    cudaGetSymbolAddress((void**)&q,   g_q);
    cudaGetSymbolAddress((void**)&qrt, g_qrt);
    cudaGetSymbolAddress((void**)&xt,  g_xt);
    cudaGetSymbolAddress((void**)&wqt, g_wqt);
    cudaGetSymbolAddress((void**)&bkw, g_bkw);
    cudaGetSymbolAddress((void**)&kwp, g_kwp);
    cudaGetSymbolAddress((void**)&wv,  g_w);
    cudaGetSymbolAddress((void**)&ktf, g_ktf);

    static bool attr_set = false;
    if (!attr_set) {
        cudaFuncSetAttribute(mega_gemm,
                             cudaFuncAttributeMaxDynamicSharedMemorySize, SMEM_PIPE);
        cudaFuncSetAttribute(scores_tc,
                             cudaFuncAttributeMaxDynamicSharedMemorySize, SMEM_PIPE);
        attr_set = true;
    }

    // merged operand prep: all four tf32/permute jobs in one launch
    prep_all<<<PREP_TOTAL, 256>>>(qr, x, wqb, wk, wpr, qrt, xt, wqt, bkw);

    // merged GEMM: q-proj (1024 blocks) + kw split-K (256 blocks)
    mega_gemm<<<1280, 256, SMEM_PIPE>>>(qrt, wqt, q, xt, bkw, kwp, cosv, sinv);

    // fused split-K reduce + layernorm + rope k + weight extraction
    ln_rope_w<<<TT, 192>>>(kwp, cosv, sinv, gam, bet, ktf, wv);

    // scores: 8 key tiles x 1024 query pairs
    scores_tc<<<dim3(SQ / 128, TT / 2), 256, SMEM_PIPE>>>(q, ktf, wv, out);
}

// round 16
// speedup vs baseline: 1.5278x; 1.5278x over previous
#include <cuda_runtime.h>
#include <cstdint>

// ---------------------------------------------------------------------------
// Problem constants
// ---------------------------------------------------------------------------
#define TT   2048      // B*S total rows
#define DIM  7168
#define NH   64        // heads
#define HD   128       // head dim
#define RD   64        // rope dims
#define QL   1536
#define HHD  8192      // NH*HD
#define SQ   1024      // sequence (per batch)
#define EPSV 1e-6f
#define SCALEV 0.08838834764831845f   // 128^-0.5
#define KSPL 8         // split-K factor for the kw GEMM

// pair permutation within 8-element k-groups: fragments (qd, qd+4) -> adjacent
#define KPERM(k) (((k) & ~7) | (((k) & 3) << 1) | (((k) >> 2) & 1))

// merged-prep grid partition
#define PREP_QR  (TT * QL / 4 / 256)            // 3072 blocks
#define PREP_X   (TT * DIM / 4 / 256)           // 14336 blocks
#define PREP_TR  ((HHD / 32) * (QL / 32))       // 12288 blocks
#define PREP_PK  (8 * (DIM / 32))               // 1792 blocks
#define PREP_TOTAL (PREP_QR + PREP_X + PREP_TR + PREP_PK)

// ---------------------------------------------------------------------------
// Scratch (device globals: allocation-free, graph-capture safe)
// ---------------------------------------------------------------------------
__device__ unsigned g_q[TT * HHD];          // 64 MB : q tf32 bits, k-permuted
__device__ unsigned g_qrt[TT * QL];         // 12.6MB: qr tf32 bits, k-permuted
__device__ unsigned g_xt[TT * DIM];         // 58 MB : x  tf32 bits, k-permuted
__device__ unsigned g_wqt[HHD * QL];        // 50 MB : Wq^T tf32 bits, k-permuted
__device__ unsigned g_bkw[256 * DIM];       // 7.3MB : (Wk||Wproj||0)^T tf32, permuted
__device__ float    g_kwp[KSPL * TT * 256]; // 16 MB : split-K partials
__device__ float    g_w[TT * NH];           // per-head weights
__device__ unsigned g_ktf[TT * HD];         // final k, tf32 bits, k-permuted

// ---------------------------------------------------------------------------
// helpers
// ---------------------------------------------------------------------------
__device__ __forceinline__ unsigned f2tf(float f) {
    unsigned u;
    asm("cvt.rna.tf32.f32 %0, %1;" : "=r"(u) : "f"(f));
    return u;
}

__device__ __forceinline__ uint32_t smem_u32(const void* p) {
    uint32_t a;
    asm("{ .reg .u64 t; cvta.to.shared.u64 t, %1; cvt.u32.u64 %0, t; }"
        : "=r"(a) : "l"(p));
    return a;
}

#define CP_ASYNC16(dst, src) \
    asm volatile("cp.async.cg.shared.global [%0], [%1], 16;" \
                 :: "r"(dst), "l"(src) : "memory")
#define CP_COMMIT() asm volatile("cp.async.commit_group;" ::: "memory")
#define CP_WAIT(n)  asm volatile("cp.async.wait_group %0;" :: "n"(n) : "memory")

__device__ __forceinline__ void mma_tf32(float c[4], const unsigned a[4],
                                         const unsigned b[2]) {
    asm volatile(
        "mma.sync.aligned.m16n8k8.row.col.f32.tf32.tf32.f32 "
        "{%0,%1,%2,%3}, {%4,%5,%6,%7}, {%8,%9}, {%0,%1,%2,%3};"
        : "+f"(c[0]), "+f"(c[1]), "+f"(c[2]), "+f"(c[3])
        : "r"(a[0]), "r"(a[1]), "r"(a[2]), "r"(a[3]), "r"(b[0]), "r"(b[1]));
}

// smem tile row stride: 32 k + 8 pad u32 = 160 B (conflict-free LDS.64 pattern)
#define RST 40
#define TS_B_OFF 20480                     // 128 * 160
#define STAGE_BYTES 40960                  // A + B tiles per stage
#define SMEM_PIPE (2 * STAGE_BYTES)        // 81920  (2 CTAs/SM -> 160KB, safe)

// ---------------------------------------------------------------------------
// MERGED operand prep: one grid, four independent jobs (tf32 + KPERM).
// ---------------------------------------------------------------------------
__global__ __launch_bounds__(256) void prep_all(const float* __restrict__ qr,
                                                const float* __restrict__ x,
                                                const float* __restrict__ wqb,
                                                const float* __restrict__ wk,
                                                const float* __restrict__ wpr,
                                                unsigned* __restrict__ qrt,
                                                unsigned* __restrict__ xt,
                                                unsigned* __restrict__ wqt,
                                                unsigned* __restrict__ bkw) {
    const int tid = threadIdx.x;
    int b = blockIdx.x;

    if (b < PREP_QR) {
        const size_t i0 = ((size_t)b * 256 + tid) * 4;
        float4 v = *(const float4*)(qr + i0);
        qrt[KPERM(i0 + 0)] = f2tf(v.x);
        qrt[KPERM(i0 + 1)] = f2tf(v.y);
        qrt[KPERM(i0 + 2)] = f2tf(v.z);
        qrt[KPERM(i0 + 3)] = f2tf(v.w);
        return;
    }
    b -= PREP_QR;
    if (b < PREP_X) {
        const size_t i0 = ((size_t)b * 256 + tid) * 4;
        float4 v = *(const float4*)(x + i0);
        xt[KPERM(i0 + 0)] = f2tf(v.x);
        xt[KPERM(i0 + 1)] = f2tf(v.y);
        xt[KPERM(i0 + 2)] = f2tf(v.z);
        xt[KPERM(i0 + 3)] = f2tf(v.w);
        return;
    }
    b -= PREP_X;

    __shared__ float tile[32][33];
    const int tx = tid & 31, ty = tid >> 5;

    if (b < PREP_TR) {
        const int n0 = (b % (HHD / 32)) * 32;
        const int k0 = (b / (HHD / 32)) * 32;
#pragma unroll
        for (int j = 0; j < 32; j += 8)
            tile[ty + j][tx] = wqb[(size_t)(k0 + ty + j) * HHD + n0 + tx];
        __syncthreads();
#pragma unroll
        for (int j = 0; j < 32; j += 8)
            wqt[(size_t)(n0 + ty + j) * QL + KPERM(k0 + tx)] = f2tf(tile[tx][ty + j]);
        return;
    }
    b -= PREP_TR;
    {
        const int n0 = (b % 8) * 32;
        const int k0 = (b / 8) * 32;
#pragma unroll
        for (int j = 0; j < 32; j += 8) {
            int k = k0 + ty + j, n = n0 + tx;
            float v = (n < HD) ? wk[(size_t)k * HD + n]
                               : ((n < HD + NH) ? wpr[(size_t)k * NH + (n - HD)] : 0.f);
            tile[ty + j][tx] = v;
        }
        __syncthreads();
#pragma unroll
        for (int j = 0; j < 32; j += 8)
            bkw[(size_t)(n0 + ty + j) * DIM + KPERM(k0 + tx)] = f2tf(tile[tx][ty + j]);
    }
}

// ---------------------------------------------------------------------------
// MERGED double-buffered mma.sync tf32 GEMM; single-sync pipeline:
//   wait(load i) -> sync -> issue load(i+1) -> MMA(i)
// ---------------------------------------------------------------------------
__global__ __launch_bounds__(256, 2) void mega_gemm(const unsigned* __restrict__ qrt,
                                                    const unsigned* __restrict__ wqt,
                                                    unsigned* __restrict__ qout,
                                                    const unsigned* __restrict__ xt,
                                                    const unsigned* __restrict__ bkw,
                                                    float* __restrict__ kwp,
                                                    const float* __restrict__ cosv,
                                                    const float* __restrict__ sinv) {
    extern __shared__ char smem[];
    const uint32_t sb = smem_u32(smem);
    const int tid = threadIdx.x;
    const int lane = tid & 31, wid = tid >> 5;
    const int warp_m = wid >> 2, warp_n = wid & 3;
    const int g = lane >> 2, qd = lane & 3;

    const int bid = blockIdx.x;
    const bool is_q = (bid < 1024);

    const unsigned *A, *B;
    int m0, n0, Ktot, nchunks, c0, N;
    float* Cf;
    if (is_q) {
        m0 = (bid >> 6) * 128;
        n0 = (bid & 63) * 128;
        Ktot = QL; nchunks = QL / 32; c0 = 0; N = HHD;
        A = qrt; B = wqt; Cf = nullptr;
    } else {
        int b2 = bid - 1024;
        int z  = b2 >> 5;
        int r  = b2 & 31;
        m0 = (r >> 1) * 128;
        n0 = (r & 1) * 128;
        Ktot = DIM; nchunks = DIM / 32 / KSPL; c0 = z * nchunks; N = 256;
        A = xt; B = bkw; Cf = kwp + (size_t)z * TT * 256;
    }

    auto load_stage = [&](int c, int s) {
        const int kt = c * 32;
        const uint32_t base = sb + s * STAGE_BYTES;
#pragma unroll
        for (int r = 0; r < 4; r++) {
            int lin = r * 256 + tid;
            int row = lin >> 3, c4 = lin & 7;
            CP_ASYNC16(base + row * 160 + c4 * 16,
                       A + (size_t)(m0 + row) * Ktot + kt + c4 * 4);
        }
#pragma unroll
        for (int r = 0; r < 4; r++) {
            int lin = r * 256 + tid;
            int row = lin >> 3, c4 = lin & 7;
            CP_ASYNC16(base + TS_B_OFF + row * 160 + c4 * 16,
                       B + (size_t)(n0 + row) * Ktot + kt + c4 * 4);
        }
        CP_COMMIT();
    };

    float acc[4][4][4];
#pragma unroll
    for (int i = 0; i < 4; i++)
#pragma unroll
        for (int j = 0; j < 4; j++)
#pragma unroll
            for (int r = 0; r < 4; r++) acc[i][j][r] = 0.f;

    load_stage(c0, 0);

    for (int i = 0; i < nchunks; i++) {
        const int s = i & 1;
        CP_WAIT(0);
        __syncthreads();
        if (i + 1 < nchunks) load_stage(c0 + i + 1, s ^ 1);

        const unsigned* As = (const unsigned*)(smem + s * STAGE_BYTES);
        const unsigned* Bs = (const unsigned*)(smem + s * STAGE_BYTES + TS_B_OFF);
#pragma unroll
        for (int k8 = 0; k8 < 4; k8++) {
            const int ko = k8 * 8 + qd * 2;
            unsigned a[4][4], b[4][2];
#pragma unroll
            for (int mt = 0; mt < 4; mt++) {
                int mrow = warp_m * 64 + mt * 16 + g;
                uint2 lo = *(const uint2*)&As[mrow * RST + ko];
                uint2 hi = *(const uint2*)&As[(mrow + 8) * RST + ko];
                a[mt][0] = lo.x; a[mt][1] = hi.x; a[mt][2] = lo.y; a[mt][3] = hi.y;
            }
#pragma unroll
            for (int nt = 0; nt < 4; nt++) {
                int ncol = warp_n * 32 + nt * 8 + g;
                uint2 bv = *(const uint2*)&Bs[ncol * RST + ko];
                b[nt][0] = bv.x; b[nt][1] = bv.y;
            }
#pragma unroll
            for (int mt = 0; mt < 4; mt++)
#pragma unroll
                for (int nt = 0; nt < 4; nt++) mma_tf32(acc[mt][nt], a[mt], b[nt]);
        }
    }

#pragma unroll
    for (int mt = 0; mt < 4; mt++) {
        int r0 = m0 + warp_m * 64 + mt * 16 + g;
#pragma unroll
        for (int nt = 0; nt < 4; nt++) {
            int cc = n0 + warp_n * 32 + nt * 8 + qd * 2;
            float v00 = acc[mt][nt][0], v01 = acc[mt][nt][1];
            float v10 = acc[mt][nt][2], v11 = acc[mt][nt][3];
            if (is_q) {
                int d = cc & (HD - 1);
                if (d < RD) {
                    float c0r = cosv[(size_t)r0 * RD + d];
                    float s0r = sinv[(size_t)r0 * RD + d];
                    float c1r = cosv[(size_t)(r0 + 8) * RD + d];
                    float s1r = sinv[(size_t)(r0 + 8) * RD + d];
                    float o00 = v00 * c0r - v01 * s0r;
                    float o01 = v01 * c0r + v00 * s0r;
                    float o10 = v10 * c1r - v11 * s1r;
                    float o11 = v11 * c1r + v10 * s1r;
                    v00 = o00; v01 = o01; v10 = o10; v11 = o11;
                }
                int p0 = KPERM(cc), p1 = KPERM(cc + 1);
                qout[(size_t)r0 * N + p0]       = f2tf(v00);
                qout[(size_t)r0 * N + p1]       = f2tf(v01);
                qout[(size_t)(r0 + 8) * N + p0] = f2tf(v10);
                qout[(size_t)(r0 + 8) * N + p1] = f2tf(v11);
            } else {
                *(float2*)(Cf + (size_t)r0 * N + cc)       = make_float2(v00, v01);
                *(float2*)(Cf + (size_t)(r0 + 8) * N + cc) = make_float2(v10, v11);
            }
        }
    }
}

// ---------------------------------------------------------------------------
// Fused: reduce split-K partials + LayerNorm + RoPE (threads 0-127 -> g_ktf)
//        + per-head weights (threads 128-191 -> g_w).
// ---------------------------------------------------------------------------
__global__ __launch_bounds__(192) void ln_rope_w(const float* __restrict__ kwp,
                                                 const float* __restrict__ cosv,
                                                 const float* __restrict__ sinv,
                                                 const float* __restrict__ gamma,
                                                 const float* __restrict__ beta,
                                                 unsigned* __restrict__ kout,
                                                 float* __restrict__ wout) {
    const int t = blockIdx.x;
    const int d = threadIdx.x;

    float v = 0.f;
#pragma unroll
    for (int z = 0; z < KSPL; z++)
        v += kwp[(size_t)z * TT * 256 + (size_t)t * 256 + d];

    __shared__ float r1[4], r2[4];
    __shared__ float ks[HD];

    if (d < HD) {
        float s1 = v, s2 = v * v;
#pragma unroll
        for (int off = 16; off; off >>= 1) {
            s1 += __shfl_xor_sync(0xffffffffu, s1, off);
            s2 += __shfl_xor_sync(0xffffffffu, s2, off);
        }
        if ((d & 31) == 0) { r1[d >> 5] = s1; r2[d >> 5] = s2; }
    }
    __syncthreads();

    if (d < HD) {
        float sum = r1[0] + r1[1] + r1[2] + r1[3];
        float sq  = r2[0] + r2[1] + r2[2] + r2[3];
        float mu  = sum * (1.f / HD);
        float var = sq * (1.f / HD) - mu * mu;
        float kn  = (v - mu) * rsqrtf(var + EPSV) * gamma[d] + beta[d];
        ks[d] = kn;
    }
    __syncthreads();

    if (d < HD) {
        float kn = ks[d];
        float out = kn;
        if (d < RD) {
            float c = cosv[t * RD + (d & ~1)];
            float s = sinv[t * RD + (d & ~1)];
            float partner = ks[d ^ 1];
            out = ((d & 1) == 0) ? (kn * c - partner * s)
                                 : (kn * c + partner * s);
        }
        kout[(size_t)t * HD + KPERM(d)] = f2tf(out);
    } else {
        wout[(size_t)t * NH + (d - HD)] = v;
    }
}

// ---------------------------------------------------------------------------
// scores: block = 2 queries (128 rows) x 128 keys, 256 threads, 2 CTAs/SM.
// Single-sync pipeline, LDS.64 fragments.
// ---------------------------------------------------------------------------
__global__ __launch_bounds__(256, 2) void scores_tc(const unsigned* __restrict__ q,
                                                    const unsigned* __restrict__ ktf,
                                                    const float* __restrict__ w,
                                                    float* __restrict__ out) {
    extern __shared__ char smem[];
    const uint32_t sb = smem_u32(smem);
    const int tid = threadIdx.x;
    const int lane = tid & 31, wid = tid >> 5;
    const int warp_m = wid >> 2, warp_n = wid & 3;
    const int g = lane >> 2, qd = lane & 3;

    const int t0 = blockIdx.y * 2;
    const int b  = t0 >> 10;
    const int k0 = blockIdx.x * 128;

    const float* wrow = w + (size_t)(t0 + warp_m) * NH;
    float w0[4], w1[4];
#pragma unroll
    for (int mt = 0; mt < 4; mt++) {
        w0[mt] = wrow[mt * 16 + g] * SCALEV;
        w1[mt] = wrow[mt * 16 + g + 8] * SCALEV;
    }

    const unsigned* qbase = q + (size_t)t0 * HHD;
    const unsigned* kbase = ktf + (size_t)(b * SQ + k0) * HD;

    auto load_stage = [&](int c, int s) {
        const int d0 = c * 32;
        const uint32_t base = sb + s * STAGE_BYTES;
#pragma unroll
        for (int r = 0; r < 4; r++) {
            int lin = r * 256 + tid;
            int row = lin >> 3, c4 = lin & 7;
            CP_ASYNC16(base + row * 160 + c4 * 16,
                       qbase + (size_t)(row >> 6) * HHD + (row & 63) * HD + d0 + c4 * 4);
        }
#pragma unroll
        for (int r = 0; r < 4; r++) {
            int lin = r * 256 + tid;
            int row = lin >> 3, c4 = lin & 7;
            CP_ASYNC16(base + TS_B_OFF + row * 160 + c4 * 16,
                       kbase + (size_t)row * HD + d0 + c4 * 4);
        }
        CP_COMMIT();
    };

    float acc[4][4][4];
#pragma unroll
    for (int i = 0; i < 4; i++)
#pragma unroll
        for (int j2 = 0; j2 < 4; j2++)
#pragma unroll
            for (int r = 0; r < 4; r++) acc[i][j2][r] = 0.f;

    load_stage(0, 0);

#pragma unroll
    for (int i = 0; i < 4; i++) {
        const int s = i & 1;
        CP_WAIT(0);
        __syncthreads();
        if (i + 1 < 4) load_stage(i + 1, s ^ 1);

        const unsigned* Qs = (const unsigned*)(smem + s * STAGE_BYTES);
        const unsigned* Ks = (const unsigned*)(smem + s * STAGE_BYTES + TS_B_OFF);
#pragma unroll
        for (int k8 = 0; k8 < 4; k8++) {
            const int ko = k8 * 8 + qd * 2;
            unsigned a[4][4], bfr[4][2];
#pragma unroll
            for (int mt = 0; mt < 4; mt++) {
                int mrow = warp_m * 64 + mt * 16 + g;
                uint2 lo = *(const uint2*)&Qs[mrow * RST + ko];
                uint2 hi = *(const uint2*)&Qs[(mrow + 8) * RST + ko];
                a[mt][0] = lo.x; a[mt][1] = hi.x; a[mt][2] = lo.y; a[mt][3] = hi.y;
            }
#pragma unroll
            for (int nt = 0; nt < 4; nt++) {
                int ncol = warp_n * 32 + nt * 8 + g;
                uint2 bv = *(const uint2*)&Ks[ncol * RST + ko];
                bfr[nt][0] = bv.x; bfr[nt][1] = bv.y;
            }
#pragma unroll
            for (int mt = 0; mt < 4; mt++)
#pragma unroll
                for (int nt = 0; nt < 4; nt++) mma_tf32(acc[mt][nt], a[mt], bfr[nt]);
        }
    }

    // weighted relu + head reduction (intra-warp shfl)
    float p[4][2];
#pragma unroll
    for (int nt = 0; nt < 4; nt++) { p[nt][0] = 0.f; p[nt][1] = 0.f; }
#pragma unroll
    for (int mt = 0; mt < 4; mt++) {
#pragma unroll
        for (int nt = 0; nt < 4; nt++) {
            p[nt][0] += w0[mt] * fmaxf(acc[mt][nt][0], 0.f)
                      + w1[mt] * fmaxf(acc[mt][nt][2], 0.f);
            p[nt][1] += w0[mt] * fmaxf(acc[mt][nt][1], 0.f)
                      + w1[mt] * fmaxf(acc[mt][nt][3], 0.f);
        }
    }
#pragma unroll
    for (int nt = 0; nt < 4; nt++) {
#pragma unroll
        for (int off = 4; off <= 16; off <<= 1) {
            p[nt][0] += __shfl_xor_sync(0xffffffffu, p[nt][0], off);
            p[nt][1] += __shfl_xor_sync(0xffffffffu, p[nt][1], off);
        }
    }

    if (lane < 4) {
        float* o = out + (size_t)(t0 + warp_m) * SQ + k0 + warp_n * 32;
#pragma unroll
        for (int nt = 0; nt < 4; nt++)
            *(float2*)(o + nt * 8 + lane * 2) = make_float2(p[nt][0], p[nt][1]);
    }
}

// ---------------------------------------------------------------------------
// launch
// ---------------------------------------------------------------------------
extern "C" void kernel_launch(void* const* d_in, const int* in_sizes, int n_in,
                              void* d_out, int out_size) {
    const float* x    = (const float*)d_in[0];   // [2048, 7168]
    const float* qr   = (const float*)d_in[1];   // [2048, 1536]
    const float* cosv = (const float*)d_in[2];   // [2048, 64]
    const float* sinv = (const float*)d_in[3];   // [2048, 64]
    const float* wqb  = (const float*)d_in[4];   // [1536, 8192]
    const float* wk   = (const float*)d_in[5];   // [7168, 128]
    const float* wpr  = (const float*)d_in[6];   // [7168, 64]
    const float* gam  = (const float*)d_in[7];   // [128]
    const float* bet  = (const float*)d_in[8];   // [128]
    float* out = (float*)d_out;

    float *kwp, *wv;
    unsigned *q, *qrt, *xt, *wqt, *bkw, *ktf;
    cudaGetSymbolAddress((void**)&q,   g_q);
    cudaGetSymbolAddress((void**)&qrt, g_qrt);
    cudaGetSymbolAddress((void**)&xt,  g_xt);
    cudaGetSymbolAddress((void**)&wqt, g_wqt);
    cudaGetSymbolAddress((void**)&bkw, g_bkw);
    cudaGetSymbolAddress((void**)&kwp, g_kwp);
    cudaGetSymbolAddress((void**)&wv,  g_w);
    cudaGetSymbolAddress((void**)&ktf, g_ktf);

    static bool attr_set = false;
    if (!attr_set) {
        cudaFuncSetAttribute(mega_gemm,
                             cudaFuncAttributeMaxDynamicSharedMemorySize, SMEM_PIPE);
        cudaFuncSetAttribute(scores_tc,
                             cudaFuncAttributeMaxDynamicSharedMemorySize, SMEM_PIPE);
        attr_set = true;
    }

    // merged operand prep: all four tf32/permute jobs in one launch
    prep_all<<<PREP_TOTAL, 256>>>(qr, x, wqb, wk, wpr, qrt, xt, wqt, bkw);

    // merged GEMM: q-proj (1024 blocks) + kw split-K (256 blocks)
    mega_gemm<<<1280, 256, SMEM_PIPE>>>(qrt, wqt, q, xt, bkw, kwp, cosv, sinv);

    // fused split-K reduce + layernorm + rope k + weight extraction
    ln_rope_w<<<TT, 192>>>(kwp, cosv, sinv, gam, bet, ktf, wv);

    // scores: 8 key tiles x 1024 query pairs
    scores_tc<<<dim3(SQ / 128, TT / 2), 256, SMEM_PIPE>>>(q, ktf, wv, out);
}